// round 6
// baseline (speedup 1.0000x reference)
#include <cuda_runtime.h>

// Scratch for v1[8, 1024] — __device__ global (no allocations allowed).
__device__ float g_v1[8 * 1024];
// Monotonic grid-barrier arrival counter. Never reset: each launch's blocks
// wait for the next multiple of GRID (1024). Replay-safe, deterministic.
__device__ unsigned long long g_arrive = 0ULL;

static constexpr int B    = 8;
static constexpr int T    = 2048;
static constexpr int C    = 1024;
static constexpr int RPB  = 16;    // rows (t values) stored per block
static constexpr int GRID = 1024;  // must equal gridDim.x; all blocks co-resident

// Fused: phase 1 = GEMV for feature d=blockIdx.x (all 8 batches),
// grid barrier, phase 2 = broadcast 16 rows of one batch.
__global__ __launch_bounds__(256, 8)
void fused_kernel(const float* __restrict__ x,
                  const float* __restrict__ W,
                  const float* __restrict__ bias,
                  float4* __restrict__ out) {
    const int d   = blockIdx.x;
    const int tid = threadIdx.x;

    // ---------- Phase 1: v1[b][d] = dot(x[b,1,:], W[d,:]) + bias[d] ----------
    {
        const float4* w4 = reinterpret_cast<const float4*>(W + (size_t)d * C);
        const float4  w  = w4[tid];

        float acc[B];
#pragma unroll
        for (int b = 0; b < B; b++) {
            // x[b, 1, :] starts at offset b*T*C + C
            const float4* x4 = reinterpret_cast<const float4*>(x + (size_t)b * T * C + C);
            const float4  xv = x4[tid];
            acc[b] = w.x * xv.x + w.y * xv.y + w.z * xv.z + w.w * xv.w;
        }

#pragma unroll
        for (int b = 0; b < B; b++) {
#pragma unroll
            for (int off = 16; off > 0; off >>= 1)
                acc[b] += __shfl_down_sync(0xffffffffu, acc[b], off);
        }

        __shared__ float sred[8][B];  // [warp][batch]
        const int warp = tid >> 5;
        const int lane = tid & 31;
        if (lane == 0) {
#pragma unroll
            for (int b = 0; b < B; b++) sred[warp][b] = acc[b];
        }
        __syncthreads();

        if (tid < B) {
            float s = 0.0f;
#pragma unroll
            for (int wdx = 0; wdx < 8; wdx++) s += sred[wdx][tid];
            g_v1[tid * C + d] = s + bias[d];
        }
    }

    // ---------- Grid barrier (all 1024 blocks resident in one wave) ----------
    __syncthreads();               // v1 stores visible to tid 0 (cta scope)
    if (tid == 0) {
        __threadfence();           // release: publish v1 gpu-wide before arrive
        unsigned long long v = atomicAdd(&g_arrive, 1ULL) + 1ULL;
        unsigned long long tgt = ((v + (GRID - 1)) / GRID) * GRID;
        volatile unsigned long long* p = &g_arrive;
        while (*p < tgt) { }
        __threadfence();           // acquire: v1 from all blocks now visible
    }
    __syncthreads();

    // ---------- Phase 2: broadcast v1[b,:] across RPB rows ----------
    // Remap blockIdx: 8 batches x 128 row-chunks.
    const int b  = blockIdx.x >> 7;          // 0..7
    const int t0 = (blockIdx.x & 127) * RPB; // 0..2032

    const float4* v4 = reinterpret_cast<const float4*>(g_v1);
    const float4  val = v4[(b << 8) + tid];  // C/4 = 256 per batch

    float4* p = out + (((size_t)b * T + t0) << 8) + tid;  // row stride 256 float4
#pragma unroll
    for (int r = 0; r < RPB; r++) {
        p[(size_t)r << 8] = val;
    }
}

extern "C" void kernel_launch(void* const* d_in, const int* in_sizes, int n_in,
                              void* d_out, int out_size) {
    const float* x    = (const float*)d_in[0];
    const float* W    = (const float*)d_in[1];
    const float* bias = (const float*)d_in[2];
    float4* out = reinterpret_cast<float4*>(d_out);

    fused_kernel<<<GRID, 256>>>(x, W, bias, out);
}

// round 10
// speedup vs baseline: 1.0332x; 1.0332x over previous
#include <cuda_runtime.h>

// Scratch for v1[8, 1024] — __device__ global (no allocations allowed).
__device__ float g_v1[8 * 1024];

static constexpr int B    = 8;
static constexpr int T    = 2048;
static constexpr int C    = 1024;
static constexpr int RPB  = 8;              // rows stored per broadcast block
static constexpr int GRID2 = B * (T / RPB); // 2048 broadcast blocks

// One block per output feature d. 256 threads, each owns one float4 of W[d,:].
// Computes v1[b][d] = dot(x[b,1,:], W[d,:]) + bias[d] for all 8 batches.
__global__ __launch_bounds__(256, 8)
void gemv_row1_kernel(const float* __restrict__ x,
                      const float* __restrict__ W,
                      const float* __restrict__ bias) {
    const int d   = blockIdx.x;
    const int tid = threadIdx.x;

    const float4* w4 = reinterpret_cast<const float4*>(W + (size_t)d * C);
    const float4  w  = w4[tid];

    float acc[B];
#pragma unroll
    for (int b = 0; b < B; b++) {
        // x[b, 1, :] starts at offset b*T*C + C
        const float4* x4 = reinterpret_cast<const float4*>(x + (size_t)b * T * C + C);
        const float4  xv = x4[tid];
        acc[b] = w.x * xv.x + w.y * xv.y + w.z * xv.z + w.w * xv.w;
    }

#pragma unroll
    for (int b = 0; b < B; b++) {
#pragma unroll
        for (int off = 16; off > 0; off >>= 1)
            acc[b] += __shfl_down_sync(0xffffffffu, acc[b], off);
    }

    __shared__ float sred[8][B];  // [warp][batch]
    const int warp = tid >> 5;
    const int lane = tid & 31;
    if (lane == 0) {
#pragma unroll
        for (int b = 0; b < B; b++) sred[warp][b] = acc[b];
    }
    __syncthreads();

    if (tid < B) {
        float s = 0.0f;
#pragma unroll
        for (int wdx = 0; wdx < 8; wdx++) s += sred[wdx][tid];
        g_v1[tid * C + d] = s + bias[d];
    }

    // Allow the dependent broadcast grid to launch once all blocks reach here.
    cudaTriggerProgrammaticLaunchCompletion();
}

// Broadcast v1[b,:] across T rows. Launched with PDL: runs prologue while
// gemv is still in flight, then waits on the grid dependency before reading v1.
__global__ __launch_bounds__(256)
void broadcast_kernel(float4* __restrict__ out) {
    const int tid = threadIdx.x;
    const int b   = blockIdx.x >> 8;            // 2048 blocks: 8 batches x 256 chunks
    const int t0  = (blockIdx.x & 255) * RPB;

    // Precompute addresses before the dependency sync (overlap with gemv).
    float4* p = out + (((size_t)b * T + t0) << 8) + tid;  // row stride 256 float4
    const float4* vsrc = reinterpret_cast<const float4*>(g_v1) + (b << 8) + tid;

    cudaGridDependencySynchronize();   // wait for gemv grid's v1 stores

    const float4 val = *vsrc;
#pragma unroll
    for (int r = 0; r < RPB; r++) {
        p[(size_t)r << 8] = val;
    }
}

extern "C" void kernel_launch(void* const* d_in, const int* in_sizes, int n_in,
                              void* d_out, int out_size) {
    const float* x    = (const float*)d_in[0];
    const float* W    = (const float*)d_in[1];
    const float* bias = (const float*)d_in[2];
    float4* out = reinterpret_cast<float4*>(d_out);

    gemv_row1_kernel<<<C, 256>>>(x, W, bias);

    // Secondary launch with programmatic stream serialization (PDL).
    cudaLaunchConfig_t cfg = {};
    cfg.gridDim  = dim3(GRID2, 1, 1);
    cfg.blockDim = dim3(256, 1, 1);
    cfg.dynamicSmemBytes = 0;
    cfg.stream = 0;  // legacy default stream (same as <<<>>> above)

    cudaLaunchAttribute attrs[1];
    attrs[0].id = cudaLaunchAttributeProgrammaticStreamSerialization;
    attrs[0].val.programmaticStreamSerializationAllowed = 1;
    cfg.attrs    = attrs;
    cfg.numAttrs = 1;

    cudaLaunchKernelEx(&cfg, broadcast_kernel, out);
}

// round 11
// speedup vs baseline: 1.1047x; 1.0692x over previous
#include <cuda_runtime.h>

// Scratch for v1[8, 1024] — __device__ global (no allocations allowed).
__device__ float g_v1[8 * 1024];

static constexpr int B    = 8;
static constexpr int T    = 2048;
static constexpr int C    = 1024;
static constexpr int RPB  = 8;              // rows stored per broadcast block
static constexpr int GRID2 = B * (T / RPB); // 2048 broadcast blocks
static constexpr int FPB  = 8;              // features per gemv block
static constexpr int GRID1 = C / FPB;       // 128 gemv blocks -> 1 CTA/SM

// GEMV: 128 blocks (<=1 per SM, no cross-CTA L1tex contention), 8 warps/block,
// warp w computes feature d = blockIdx.x*8 + w for all 8 batches.
// x rows are staged once in smem (32 KB) and reused by all 8 warps.
__global__ __launch_bounds__(256, 1)
void gemv_row1_kernel(const float* __restrict__ x,
                      const float* __restrict__ W,
                      const float* __restrict__ bias) {
    __shared__ float4 xs4[B][C / 4];   // 32 KB

    const int tid  = threadIdx.x;
    const int warp = tid >> 5;
    const int lane = tid & 31;

    // Stage x[b,1,:] into smem: thread t loads one float4 per batch.
#pragma unroll
    for (int b = 0; b < B; b++) {
        const float4* xr = reinterpret_cast<const float4*>(x + (size_t)b * T * C + C);
        xs4[b][tid] = xr[tid];
    }
    __syncthreads();

    const int d = blockIdx.x * FPB + warp;

    // Prefetch this feature's W row: lane l owns float4s {l + 32*i}, i=0..7.
    const float4* w4 = reinterpret_cast<const float4*>(W + (size_t)d * C);
    float4 w[8];
#pragma unroll
    for (int i = 0; i < 8; i++) w[i] = w4[lane + 32 * i];

    float acc[B];
#pragma unroll
    for (int b = 0; b < B; b++) acc[b] = 0.0f;

#pragma unroll
    for (int i = 0; i < 8; i++) {
#pragma unroll
        for (int b = 0; b < B; b++) {
            const float4 xv = xs4[b][lane + 32 * i];
            acc[b] += w[i].x * xv.x + w[i].y * xv.y + w[i].z * xv.z + w[i].w * xv.w;
        }
    }

    // Warp reduce each batch accumulator.
#pragma unroll
    for (int b = 0; b < B; b++) {
#pragma unroll
        for (int off = 16; off > 0; off >>= 1)
            acc[b] += __shfl_down_sync(0xffffffffu, acc[b], off);
    }

    if (lane == 0) {
        const float bv = bias[d];
#pragma unroll
        for (int b = 0; b < B; b++)
            g_v1[b * C + d] = acc[b] + bv;
    }
}

// Broadcast v1[b,:] across T rows. Each block: one batch, RPB rows.
// Each thread loads its float4 of v1[b] once, then RPB independent STG.128s.
__global__ __launch_bounds__(256)
void broadcast_kernel(float4* __restrict__ out) {
    const int tid = threadIdx.x;
    const int b   = blockIdx.x >> 8;            // 2048 blocks: 8 batches x 256 chunks
    const int t0  = (blockIdx.x & 255) * RPB;

    const float4* v4 = reinterpret_cast<const float4*>(g_v1);
    const float4  val = v4[(b << 8) + tid];     // C/4 = 256 per batch

    float4* p = out + (((size_t)b * T + t0) << 8) + tid;  // row stride 256 float4
#pragma unroll
    for (int r = 0; r < RPB; r++) {
        p[(size_t)r << 8] = val;
    }
}

extern "C" void kernel_launch(void* const* d_in, const int* in_sizes, int n_in,
                              void* d_out, int out_size) {
    const float* x    = (const float*)d_in[0];
    const float* W    = (const float*)d_in[1];
    const float* bias = (const float*)d_in[2];
    float4* out = reinterpret_cast<float4*>(d_out);

    gemv_row1_kernel<<<GRID1, 256>>>(x, W, bias);
    broadcast_kernel<<<GRID2, 256>>>(out);
}

// round 12
// speedup vs baseline: 1.1214x; 1.0152x over previous
#include <cuda_runtime.h>

static constexpr int B = 8;
static constexpr int T = 2048;
static constexpr int C = 1024;
static constexpr int DPB = 64;              // features per block
static constexpr int NCHUNK = C / DPB;      // 16 slabs
static constexpr int GRID = B * NCHUNK;     // 128 blocks -> one wave, ~1/SM

// Fully fused, barrier-free: each block computes v1[b, d0:d0+64) itself and
// broadcasts exactly those features across all T rows. No inter-block deps.
__global__ __launch_bounds__(256, 1)
void fused_slab_kernel(const float* __restrict__ x,
                       const float* __restrict__ W,
                       const float* __restrict__ bias,
                       float4* __restrict__ out) {
    __shared__ float4 xs[C / 4];     // 4 KB: x[b, 1, :]
    __shared__ float  slab[DPB];     // v1[b, d0:d0+DPB)

    const int tid  = threadIdx.x;
    const int warp = tid >> 5;
    const int lane = tid & 31;
    const int b    = blockIdx.x >> 4;          // 0..7
    const int d0   = (blockIdx.x & 15) * DPB;  // 0..960

    // ---- Stage x[b,1,:] (starts at offset b*T*C + C) ----
    xs[tid] = reinterpret_cast<const float4*>(x + (size_t)b * T * C + C)[tid];
    __syncthreads();

    // ---- GEMV: warp w computes features d0 + w*8 + j, j=0..7 ----
    const int dbase = d0 + warp * 8;
    float acc[8];
#pragma unroll
    for (int j = 0; j < 8; j++) acc[j] = 0.0f;

#pragma unroll
    for (int j = 0; j < 8; j++) {
        const float4* w4 = reinterpret_cast<const float4*>(W + (size_t)(dbase + j) * C);
#pragma unroll
        for (int i = 0; i < 8; i++) {
            const float4 wv = w4[lane + 32 * i];
            const float4 xv = xs[lane + 32 * i];
            acc[j] += wv.x * xv.x + wv.y * xv.y + wv.z * xv.z + wv.w * xv.w;
        }
    }

#pragma unroll
    for (int j = 0; j < 8; j++) {
#pragma unroll
        for (int off = 16; off > 0; off >>= 1)
            acc[j] += __shfl_down_sync(0xffffffffu, acc[j], off);
    }
    if (lane == 0) {
#pragma unroll
        for (int j = 0; j < 8; j++)
            slab[warp * 8 + j] = acc[j] + bias[dbase + j];
    }
    __syncthreads();

    // ---- Broadcast: 64-float slab -> out[b, t, d0:d0+64) for all t ----
    // Thread covers float4 index (tid&15) of the slab, rows (tid>>4) + 16k.
    // Warp = two contiguous 256B segments per iteration; 128 independent STGs.
    const int f4 = tid & 15;
    const int r0 = tid >> 4;
    const float4 val = reinterpret_cast<const float4*>(slab)[f4];

    float4* p = out + ((size_t)b * T + r0) * (C / 4) + (d0 >> 2) + f4;
    const size_t stride = (size_t)16 * (C / 4);   // 16 rows per iteration
#pragma unroll 16
    for (int k = 0; k < T / 16; k++) {
        p[k * stride] = val;
    }
}

extern "C" void kernel_launch(void* const* d_in, const int* in_sizes, int n_in,
                              void* d_out, int out_size) {
    const float* x    = (const float*)d_in[0];
    const float* W    = (const float*)d_in[1];
    const float* bias = (const float*)d_in[2];
    float4* out = reinterpret_cast<float4*>(d_out);

    fused_slab_kernel<<<GRID, 256>>>(x, W, bias, out);
}